// round 13
// baseline (speedup 1.0000x reference)
#include <cuda_runtime.h>
#include <math.h>

// N = 100000 nodes, E = 3200000 edges.
// g_packed[i] = {copysign(l_i, qw_i), qx, qy, qz} (16B fp32 node record; l>=0
//   so its sign bit carries qw's sign; qw rebuilt from unit-norm invariant).
// g_q[i] = {sumQ0..3}, g_zl[i] = {Z, sumL}: initialized by prep with the exact
//   self term (overwrite semantics -> graph-replay robust), accumulated by
//   edge REDs, read-only in finalize.
// Edge/final launched with PDL: they start while the predecessor still runs,
// do their independent prelude, then griddepcontrol.wait before consuming.
#define MAXN 131072
__device__ float4 g_packed[MAXN];
__device__ float4 g_q[MAXN];
__device__ float2 g_zl[MAXN];

#define TEMP 10.0f

__device__ __forceinline__ void prep_node(int i, float l, float4 q) {
    float es = __expf(TEMP * l);
    g_q[i]  = make_float4(es * q.x, es * q.y, es * q.z, es * q.w);
    g_zl[i] = make_float2(es, es * l);
    g_packed[i] = make_float4(copysignf(l, q.x), q.y, q.z, q.w);
}

// ---------------------------------------------------------------------------
// Prep: 2 nodes/thread, batched loads for MLP. node_q rows are (w,x,y,z).
// ---------------------------------------------------------------------------
__global__ void __launch_bounds__(256) prep_kernel(
    const float* __restrict__ node_levels,
    const float4* __restrict__ node_q,
    int N) {
    int t = blockIdx.x * blockDim.x + threadIdx.x;
    int i = 2 * t;
    if (i >= N) return;
    if (i + 1 < N) {
        float2 l2 = __ldg(&((const float2*)node_levels)[t]);
        float4 qa = __ldg(&node_q[i]);
        float4 qb = __ldg(&node_q[i + 1]);
        prep_node(i, l2.x, qa);
        prep_node(i + 1, l2.y, qb);
    } else {
        prep_node(i, __ldg(&node_levels[i]), __ldg(&node_q[i]));
    }
}

// ---------------------------------------------------------------------------
// Edge scatter, 2 edges per thread. Coalesced stream loads issue BEFORE the
// griddepcontrol.wait (they don't depend on prep); the random g_packed gather
// and the REDs come after.  ONE random 16B gather + v4 RED + v2 RED per edge.
// Logits bounded in [0,10) -> stable-softmax max subtraction cancels, omitted.
// ---------------------------------------------------------------------------
__device__ __forceinline__ void edge_body(int s, int d, float4 a, float w) {
    float4 p = __ldg(&g_packed[s]);
    float l  = fabsf(p.x);
    float bx = p.y, by = p.z, bz = p.w;
    float t  = 1.0f - (bx * bx + by * by + bz * bz);
    float bw = copysignf(sqrtf(fmaxf(t, 0.0f)), p.x);

    float aw = a.x, ax = a.y, ay = a.z, az = a.w;
    float cw = aw * bw - ax * bx - ay * by - az * bz;
    float cx = aw * bx + ax * bw + ay * bz - az * by;
    float cy = aw * by - ax * bz + ay * bw + az * bx;
    float cz = aw * bz + ax * by - ay * bx + az * bw;

    float ex = __expf(TEMP * w * l);

    asm volatile("red.global.add.v4.f32 [%0], {%1, %2, %3, %4};"
                 :: "l"(&g_q[d]), "f"(ex * cw), "f"(ex * cx),
                    "f"(ex * cy), "f"(ex * cz)
                 : "memory");
    asm volatile("red.global.add.v2.f32 [%0], {%1, %2};"
                 :: "l"(&g_zl[d]), "f"(ex), "f"(ex * l)
                 : "memory");
}

__global__ void __launch_bounds__(256) edge_kernel(
    const float4* __restrict__ edge_rel_q,
    const float* __restrict__ edge_w,
    const int* __restrict__ src,
    const int* __restrict__ dst,
    int E) {
    int t = blockIdx.x * blockDim.x + threadIdx.x;
    int e = 2 * t;
    if (e >= E) {
        asm volatile("griddepcontrol.wait;" ::: "memory");
        return;
    }

    if (e + 1 < E) {
        int2   s2 = __ldg(&((const int2*)src)[t]);
        int2   d2 = __ldg(&((const int2*)dst)[t]);
        float2 w2 = __ldg(&((const float2*)edge_w)[t]);
        float4 a0 = __ldg(&edge_rel_q[e]);
        float4 a1 = __ldg(&edge_rel_q[e + 1]);
        // prep must be fully visible before gathering g_packed / RED'ing g_q
        asm volatile("griddepcontrol.wait;" ::: "memory");
        edge_body(s2.x, d2.x, a0, w2.x);
        edge_body(s2.y, d2.y, a1, w2.y);
    } else {
        int    s0 = __ldg(&src[e]);
        int    d0 = __ldg(&dst[e]);
        float  w0 = __ldg(&edge_w[e]);
        float4 a0 = __ldg(&edge_rel_q[e]);
        asm volatile("griddepcontrol.wait;" ::: "memory");
        edge_body(s0, d0, a0, w0);
    }
}

// ---------------------------------------------------------------------------
// Finalize: read-only on accumulators (self term already inside).
//   out_q = normalize(sum_q)            (Z cancels inside normalize)
//   out_levels = sumL / Z
// Output layout: out[0..4N) = out_q row-major, out[4N..5N) = out_levels.
// ---------------------------------------------------------------------------
__global__ void __launch_bounds__(256) final_kernel(float* __restrict__ out,
                                                   int N) {
    int i = blockIdx.x * blockDim.x + threadIdx.x;
    asm volatile("griddepcontrol.wait;" ::: "memory");
    if (i >= N) return;

    float4 acc = g_q[i];
    float2 zl  = g_zl[i];

    float n2 = acc.x * acc.x + acc.y * acc.y + acc.z * acc.z + acc.w * acc.w;
    float inv = rsqrtf(fmaxf(n2, 1e-24f));
    ((float4*)out)[i] = make_float4(acc.x * inv, acc.y * inv,
                                    acc.z * inv, acc.w * inv);
    out[4 * N + i] = __fdividef(zl.y, zl.x);
}

extern "C" void kernel_launch(void* const* d_in, const int* in_sizes, int n_in,
                              void* d_out, int out_size) {
    const float*  node_levels = (const float*)d_in[0];
    const float4* node_q      = (const float4*)d_in[1];
    const float4* edge_rel_q  = (const float4*)d_in[2];
    const float*  edge_w      = (const float*)d_in[3];
    const int*    src         = (const int*)d_in[4];
    const int*    dst         = (const int*)d_in[5];

    int N = in_sizes[0];
    int E = in_sizes[3];

    float* out = (float*)d_out;

    const int T = 256;

    // prep: plain launch
    int prep_threads = (N + 1) / 2;
    prep_kernel<<<(prep_threads + T - 1) / T, T>>>(node_levels, node_q, N);

    // edge + final: PDL (programmatic stream serialization)
    cudaLaunchAttribute attr[1];
    attr[0].id = cudaLaunchAttributeProgrammaticStreamSerialization;
    attr[0].val.programmaticStreamSerializationAllowed = 1;

    int edge_threads = (E + 1) / 2;
    cudaLaunchConfig_t cfg_e = {};
    cfg_e.gridDim  = dim3((edge_threads + T - 1) / T);
    cfg_e.blockDim = dim3(T);
    cfg_e.stream   = 0;
    cfg_e.attrs    = attr;
    cfg_e.numAttrs = 1;
    cudaLaunchKernelEx(&cfg_e, edge_kernel, edge_rel_q, edge_w, src, dst, E);

    cudaLaunchConfig_t cfg_f = {};
    cfg_f.gridDim  = dim3((N + T - 1) / T);
    cfg_f.blockDim = dim3(T);
    cfg_f.stream   = 0;
    cfg_f.attrs    = attr;
    cfg_f.numAttrs = 1;
    cudaLaunchKernelEx(&cfg_f, final_kernel, out, N);
}

// round 14
// speedup vs baseline: 1.0458x; 1.0458x over previous
#include <cuda_runtime.h>
#include <math.h>

// N = 100000 nodes, E = 3200000 edges.
// g_packed[i] = {copysign(l_i, qw_i), qx, qy, qz} (16B fp32 node record; l>=0
//   so its sign bit carries qw's sign; qw rebuilt from unit-norm invariant).
// g_q[i] = {sumQ0..3}, g_zl[i] = {Z, sumL}: initialized by prep with the exact
//   self term (overwrite semantics -> graph-replay robust), accumulated by
//   edge REDs, read-only in finalize.
// PDL: prep signals launch_dependents at block start (all blocks wave-1
//   resident -> edge launches ~immediately and overlaps); edge's coalesced
//   stream loads precede its griddepcontrol.wait, which guarantees all of
//   prep's stores are visible before the g_packed gather / REDs.
#define MAXN 131072
__device__ float4 g_packed[MAXN];
__device__ float4 g_q[MAXN];
__device__ float2 g_zl[MAXN];

#define TEMP 10.0f

// ---------------------------------------------------------------------------
// Prep: 1 node/thread (R13 showed 2/thread hurts occupancy).
// node_q rows are (w,x,y,z).
// ---------------------------------------------------------------------------
__global__ void __launch_bounds__(256) prep_kernel(
    const float* __restrict__ node_levels,
    const float4* __restrict__ node_q,
    int N) {
    // Signal dependents as early as possible; griddepcontrol.wait in the
    // dependent still guarantees visibility of ALL of this grid's stores.
    asm volatile("griddepcontrol.launch_dependents;" ::: "memory");

    int i = blockIdx.x * blockDim.x + threadIdx.x;
    if (i >= N) return;
    float l  = __ldg(&node_levels[i]);
    float4 q = __ldg(&node_q[i]);
    float es = __expf(TEMP * l);

    g_q[i]  = make_float4(es * q.x, es * q.y, es * q.z, es * q.w);
    g_zl[i] = make_float2(es, es * l);
    g_packed[i] = make_float4(copysignf(l, q.x), q.y, q.z, q.w);
}

// ---------------------------------------------------------------------------
// Edge scatter, 2 edges per thread. Coalesced stream loads issue BEFORE the
// griddepcontrol.wait; the random g_packed gather and the REDs come after.
// ONE random 16B gather + v4 RED + v2 RED per edge.
// Logits bounded in [0,10) -> stable-softmax max subtraction cancels, omitted.
// ---------------------------------------------------------------------------
__device__ __forceinline__ void edge_body(int s, int d, float4 a, float w) {
    float4 p = __ldg(&g_packed[s]);
    float l  = fabsf(p.x);
    float bx = p.y, by = p.z, bz = p.w;
    float t  = 1.0f - (bx * bx + by * by + bz * bz);
    float bw = copysignf(sqrtf(fmaxf(t, 0.0f)), p.x);

    float aw = a.x, ax = a.y, ay = a.z, az = a.w;
    float cw = aw * bw - ax * bx - ay * by - az * bz;
    float cx = aw * bx + ax * bw + ay * bz - az * by;
    float cy = aw * by - ax * bz + ay * bw + az * bx;
    float cz = aw * bz + ax * by - ay * bx + az * bw;

    float ex = __expf(TEMP * w * l);

    asm volatile("red.global.add.v4.f32 [%0], {%1, %2, %3, %4};"
                 :: "l"(&g_q[d]), "f"(ex * cw), "f"(ex * cx),
                    "f"(ex * cy), "f"(ex * cz)
                 : "memory");
    asm volatile("red.global.add.v2.f32 [%0], {%1, %2};"
                 :: "l"(&g_zl[d]), "f"(ex), "f"(ex * l)
                 : "memory");
}

__global__ void __launch_bounds__(256) edge_kernel(
    const float4* __restrict__ edge_rel_q,
    const float* __restrict__ edge_w,
    const int* __restrict__ src,
    const int* __restrict__ dst,
    int E) {
    int t = blockIdx.x * blockDim.x + threadIdx.x;
    int e = 2 * t;
    if (e >= E) {
        asm volatile("griddepcontrol.wait;" ::: "memory");
        return;
    }

    if (e + 1 < E) {
        int2   s2 = __ldg(&((const int2*)src)[t]);
        int2   d2 = __ldg(&((const int2*)dst)[t]);
        float2 w2 = __ldg(&((const float2*)edge_w)[t]);
        float4 a0 = __ldg(&edge_rel_q[e]);
        float4 a1 = __ldg(&edge_rel_q[e + 1]);
        // prep must be fully visible before gathering g_packed / RED'ing g_q
        asm volatile("griddepcontrol.wait;" ::: "memory");
        edge_body(s2.x, d2.x, a0, w2.x);
        edge_body(s2.y, d2.y, a1, w2.y);
    } else {
        int    s0 = __ldg(&src[e]);
        int    d0 = __ldg(&dst[e]);
        float  w0 = __ldg(&edge_w[e]);
        float4 a0 = __ldg(&edge_rel_q[e]);
        asm volatile("griddepcontrol.wait;" ::: "memory");
        edge_body(s0, d0, a0, w0);
    }
}

// ---------------------------------------------------------------------------
// Finalize: read-only on accumulators (self term already inside).
//   out_q = normalize(sum_q)            (Z cancels inside normalize)
//   out_levels = sumL / Z
// Output layout: out[0..4N) = out_q row-major, out[4N..5N) = out_levels.
// edge_kernel does NOT signal early, so this launches at edge completion;
// the wait is a cheap correctness guarantee.
// ---------------------------------------------------------------------------
__global__ void __launch_bounds__(256) final_kernel(float* __restrict__ out,
                                                   int N) {
    int i = blockIdx.x * blockDim.x + threadIdx.x;
    asm volatile("griddepcontrol.wait;" ::: "memory");
    if (i >= N) return;

    float4 acc = g_q[i];
    float2 zl  = g_zl[i];

    float n2 = acc.x * acc.x + acc.y * acc.y + acc.z * acc.z + acc.w * acc.w;
    float inv = rsqrtf(fmaxf(n2, 1e-24f));
    ((float4*)out)[i] = make_float4(acc.x * inv, acc.y * inv,
                                    acc.z * inv, acc.w * inv);
    out[4 * N + i] = __fdividef(zl.y, zl.x);
}

extern "C" void kernel_launch(void* const* d_in, const int* in_sizes, int n_in,
                              void* d_out, int out_size) {
    const float*  node_levels = (const float*)d_in[0];
    const float4* node_q      = (const float4*)d_in[1];
    const float4* edge_rel_q  = (const float4*)d_in[2];
    const float*  edge_w      = (const float*)d_in[3];
    const int*    src         = (const int*)d_in[4];
    const int*    dst         = (const int*)d_in[5];

    int N = in_sizes[0];
    int E = in_sizes[3];

    float* out = (float*)d_out;

    const int T = 256;

    // prep: plain launch, 1 node/thread
    prep_kernel<<<(N + T - 1) / T, T>>>(node_levels, node_q, N);

    // edge + final: PDL (programmatic stream serialization)
    cudaLaunchAttribute attr[1];
    attr[0].id = cudaLaunchAttributeProgrammaticStreamSerialization;
    attr[0].val.programmaticStreamSerializationAllowed = 1;

    int edge_threads = (E + 1) / 2;
    cudaLaunchConfig_t cfg_e = {};
    cfg_e.gridDim  = dim3((edge_threads + T - 1) / T);
    cfg_e.blockDim = dim3(T);
    cfg_e.stream   = 0;
    cfg_e.attrs    = attr;
    cfg_e.numAttrs = 1;
    cudaLaunchKernelEx(&cfg_e, edge_kernel, edge_rel_q, edge_w, src, dst, E);

    cudaLaunchConfig_t cfg_f = {};
    cfg_f.gridDim  = dim3((N + T - 1) / T);
    cfg_f.blockDim = dim3(T);
    cfg_f.stream   = 0;
    cfg_f.attrs    = attr;
    cfg_f.numAttrs = 1;
    cudaLaunchKernelEx(&cfg_f, final_kernel, out, N);
}